// round 12
// baseline (speedup 1.0000x reference)
#include <cuda_runtime.h>
#include <cuda_fp16.h>
#include <cstdint>

// Problem constants
#define NI      100000      // item count
#define NU      131072      // user count
#define NE      64          // embedding size
#define NNZ_S   1500000     // I * TOPK
#define NNZ_U   4194304     // user-item interactions (= 2^22)

#define BT 256

// Prologue region sizes
#define UVM_BLOCKS  (NNZ_U / BT)              // one edge per thread
#define RP_TOTAL    ((NI + 1) + (NU + 1))
#define RP_BLOCKS   ((RP_TOTAL + BT - 1) / BT)
#define CV_TOTAL    (NI * NE / 2)             // one half2 per thread
#define CV_BLOCKS   ((CV_TOTAL + BT - 1) / BT)

// ---------------------------------------------------------------------------
// Static device scratch (allocation-free rule)
// x stored as half: one row = 64 halves = 8 uint4.
// ---------------------------------------------------------------------------
__device__ uint4    g_xh0[NI * NE / 8];       // 12.8 MB (half storage)
__device__ uint4    g_xh1[NI * NE / 8];       // 12.8 MB
__device__ unsigned g_mask[NNZ_U / 32 + 1];   // 512 KB keep-bits (+1 pad word)
__device__ int      g_s_rowptr[NI + 1];
__device__ int      g_u_rowptr[NU + 1];

// ---------------------------------------------------------------------------
// threefry2x32 (exact JAX implementation, key = (0, 42))
// ---------------------------------------------------------------------------
__device__ __forceinline__ uint32_t rotl32(uint32_t x, int d) {
    return (x << d) | (x >> (32 - d));
}

__device__ __forceinline__ void threefry2x32(uint32_t k0, uint32_t k1,
                                             uint32_t x0, uint32_t x1,
                                             uint32_t& o0, uint32_t& o1) {
    uint32_t ks2 = k0 ^ k1 ^ 0x1BD11BDAu;
    x0 += k0; x1 += k1;
    x0 += x1; x1 = rotl32(x1, 13); x1 ^= x0;
    x0 += x1; x1 = rotl32(x1, 15); x1 ^= x0;
    x0 += x1; x1 = rotl32(x1, 26); x1 ^= x0;
    x0 += x1; x1 = rotl32(x1,  6); x1 ^= x0;
    x0 += k1; x1 += ks2 + 1u;
    x0 += x1; x1 = rotl32(x1, 17); x1 ^= x0;
    x0 += x1; x1 = rotl32(x1, 29); x1 ^= x0;
    x0 += x1; x1 = rotl32(x1, 16); x1 ^= x0;
    x0 += x1; x1 = rotl32(x1, 24); x1 ^= x0;
    x0 += ks2; x1 += k0 + 2u;
    x0 += x1; x1 = rotl32(x1, 13); x1 ^= x0;
    x0 += x1; x1 = rotl32(x1, 15); x1 ^= x0;
    x0 += x1; x1 = rotl32(x1, 26); x1 ^= x0;
    x0 += x1; x1 = rotl32(x1,  6); x1 ^= x0;
    x0 += k0; x1 += k1 + 3u;
    x0 += x1; x1 = rotl32(x1, 17); x1 ^= x0;
    x0 += x1; x1 = rotl32(x1, 29); x1 ^= x0;
    x0 += x1; x1 = rotl32(x1, 16); x1 ^= x0;
    x0 += x1; x1 = rotl32(x1, 24); x1 ^= x0;
    x0 += k1; x1 += ks2 + 4u;
    x0 += x1; x1 = rotl32(x1, 13); x1 ^= x0;
    x0 += x1; x1 = rotl32(x1, 15); x1 ^= x0;
    x0 += x1; x1 = rotl32(x1, 26); x1 ^= x0;
    x0 += x1; x1 = rotl32(x1,  6); x1 ^= x0;
    x0 += ks2; x1 += k0 + 5u;
    o0 = x0; o1 = x1;
}

// ---------------------------------------------------------------------------
// Fused prologue kernel, 3 regions (R10 structure):
//  A: keep-bit mask (ballot) for JAX-partitionable-threefry dropout
//  B: CSR row-pointer build (S then URM) via lower_bound (+ mask pad word)
//  C: item_emb (fp32) -> half conversion into g_xh0
// ---------------------------------------------------------------------------
__global__ void prologue_kernel(unsigned* __restrict__ mask,
                                const int* __restrict__ s_rows,
                                const int* __restrict__ u_rows,
                                int* __restrict__ s_rowptr,
                                int* __restrict__ u_rowptr,
                                const float* __restrict__ item_emb,
                                __half2* __restrict__ xh) {
    int b = blockIdx.x;
    if (b < UVM_BLOCKS) {
        int i = b * BT + (int)threadIdx.x;       // i < NNZ_U exactly (full warps)
        uint32_t o0, o1;
        threefry2x32(0u, 42u, 0u, (uint32_t)i, o0, o1);
        uint32_t bits = o0 ^ o1;
        float u = __uint_as_float((bits >> 9) | 0x3F800000u) - 1.0f;
        unsigned bal = __ballot_sync(0xFFFFFFFFu, u < 0.8f);
        if ((threadIdx.x & 31) == 0) mask[i >> 5] = bal;
    } else if (b < UVM_BLOCKS + RP_BLOCKS) {
        int t = (b - UVM_BLOCKS) * BT + (int)threadIdx.x;
        if (t == 0) mask[NNZ_U / 32] = 0u;       // pad word (value unused)
        if (t <= NI) {
            int lo = 0, hi = NNZ_S;
            while (lo < hi) {
                int mid = (lo + hi) >> 1;
                if (s_rows[mid] < t) lo = mid + 1; else hi = mid;
            }
            s_rowptr[t] = lo;
        }
        int r = t - (NI + 1);
        if (r >= 0 && r <= NU) {
            int lo = 0, hi = NNZ_U;
            while (lo < hi) {
                int mid = (lo + hi) >> 1;
                if (u_rows[mid] < r) lo = mid + 1; else hi = mid;
            }
            u_rowptr[r] = lo;
        }
    } else {
        int t = (b - UVM_BLOCKS - RP_BLOCKS) * BT + (int)threadIdx.x;
        if (t >= CV_TOTAL) return;
        float2 f = *(const float2*)(item_emb + (size_t)t * 2);
        xh[t] = __float22half2_rn(f);
    }
}

// ---------------------------------------------------------------------------
// 8-lane-group-per-row segmented SpMM on half x (R10 structure) with
// software-pipelined cols/vals. __launch_bounds__(256, 6) caps registers at
// 42 to raise occupancy from 5 to 6 blocks/SM (latency-bound kernel).
// ---------------------------------------------------------------------------
template <bool WRITE_H, bool WRITE_F>
__global__ void __launch_bounds__(256, 6) spmm_h_kernel(
                            const int*   __restrict__ rowptr,
                            const int*   __restrict__ cols,
                            const float* __restrict__ vals,
                            const uint4* __restrict__ xh,
                            uint4*       __restrict__ yh,
                            float*       __restrict__ yf,
                            int n_rows) {
    int grp = (int)((blockIdx.x * blockDim.x + threadIdx.x) >> 3);  // row id
    int sub = threadIdx.x & 7;                                      // uint4 slot
    if (grp >= n_rows) return;

    int beg = rowptr[grp];
    int end = rowptr[grp + 1];

    float2 a0 = {0.f, 0.f}, a1 = {0.f, 0.f}, a2 = {0.f, 0.f}, a3 = {0.f, 0.f};

    // Preload first index batch
    int   c0 = 0, c1 = 0, c2 = 0, c3 = 0;
    float v0 = 0.f, v1 = 0.f, v2 = 0.f, v3 = 0.f;
    if (beg     < end) { c0 = __ldg(cols + beg);     v0 = __ldg(vals + beg);     }
    if (beg + 1 < end) { c1 = __ldg(cols + beg + 1); v1 = __ldg(vals + beg + 1); }
    if (beg + 2 < end) { c2 = __ldg(cols + beg + 2); v2 = __ldg(vals + beg + 2); }
    if (beg + 3 < end) { c3 = __ldg(cols + beg + 3); v3 = __ldg(vals + beg + 3); }

    for (int i = beg; i < end; i += 4) {
        // Prefetch next index batch (independent of current gathers)
        int n = i + 4;
        int   d0 = 0, d1 = 0, d2 = 0, d3 = 0;
        float w0 = 0.f, w1 = 0.f, w2 = 0.f, w3 = 0.f;
        if (n     < end) { d0 = __ldg(cols + n);     w0 = __ldg(vals + n);     }
        if (n + 1 < end) { d1 = __ldg(cols + n + 1); w1 = __ldg(vals + n + 1); }
        if (n + 2 < end) { d2 = __ldg(cols + n + 2); w2 = __ldg(vals + n + 2); }
        if (n + 3 < end) { d3 = __ldg(cols + n + 3); w3 = __ldg(vals + n + 3); }

        #define ACC_ONE(c, v)                                                  \
        {                                                                      \
            uint4 q = __ldg(xh + (size_t)(c) * 8 + sub);                       \
            float2 f0 = __half22float2(*(const __half2*)&q.x);                 \
            float2 f1 = __half22float2(*(const __half2*)&q.y);                 \
            float2 f2 = __half22float2(*(const __half2*)&q.z);                 \
            float2 f3 = __half22float2(*(const __half2*)&q.w);                 \
            a0.x = fmaf((v), f0.x, a0.x); a0.y = fmaf((v), f0.y, a0.y);        \
            a1.x = fmaf((v), f1.x, a1.x); a1.y = fmaf((v), f1.y, a1.y);        \
            a2.x = fmaf((v), f2.x, a2.x); a2.y = fmaf((v), f2.y, a2.y);        \
            a3.x = fmaf((v), f3.x, a3.x); a3.y = fmaf((v), f3.y, a3.y);        \
        }
        ACC_ONE(c0, v0)
        ACC_ONE(c1, v1)
        ACC_ONE(c2, v2)
        ACC_ONE(c3, v3)
        #undef ACC_ONE

        c0 = d0; c1 = d1; c2 = d2; c3 = d3;
        v0 = w0; v1 = w1; v2 = w2; v3 = w3;
    }

    if (WRITE_H) {
        __half2 h0 = __float22half2_rn(a0);
        __half2 h1 = __float22half2_rn(a1);
        __half2 h2 = __float22half2_rn(a2);
        __half2 h3 = __float22half2_rn(a3);
        uint4 q;
        q.x = *(const uint32_t*)&h0;
        q.y = *(const uint32_t*)&h1;
        q.z = *(const uint32_t*)&h2;
        q.w = *(const uint32_t*)&h3;
        yh[(size_t)grp * 8 + sub] = q;
    }
    if (WRITE_F) {
        float4 f0 = make_float4(a0.x, a0.y, a1.x, a1.y);
        float4 f1 = make_float4(a2.x, a2.y, a3.x, a3.y);
        *(float4*)(yf + (size_t)grp * NE + sub * 8)     = f0;
        *(float4*)(yf + (size_t)grp * NE + sub * 8 + 4) = f1;
    }
}

// ---------------------------------------------------------------------------
// U-spmm (R10 structure): index-stream pipelining; dropout via bitmask with
// funnelshift. Kept edges accumulate unscaled; exact 1.25 scale at the end.
// __launch_bounds__(256, 6) as above.
// ---------------------------------------------------------------------------
__global__ void __launch_bounds__(256, 6) spmm_u_kernel(
                            const int*      __restrict__ rowptr,
                            const int*      __restrict__ cols,
                            const unsigned* __restrict__ mask,
                            const uint4*    __restrict__ xh,
                            float*          __restrict__ yf,
                            int n_rows) {
    int grp = (int)((blockIdx.x * blockDim.x + threadIdx.x) >> 3);  // row id
    int sub = threadIdx.x & 7;                                      // uint4 slot
    if (grp >= n_rows) return;

    int beg = rowptr[grp];
    int end = rowptr[grp + 1];

    float2 a0 = {0.f, 0.f}, a1 = {0.f, 0.f}, a2 = {0.f, 0.f}, a3 = {0.f, 0.f};

    #define LOAD_BATCH(base, BITS, C0, C1, C2, C3)                             \
    {                                                                          \
        if ((base) < end) {                                                    \
            unsigned w  = (unsigned)(base) >> 5;                               \
            unsigned sh = (unsigned)(base) & 31u;                              \
            unsigned m0 = __ldg(mask + w);                                     \
            unsigned m1 = __ldg(mask + w + 1);                                 \
            BITS = __funnelshift_r(m0, m1, sh);                                \
            int rem = end - (base); if (rem > 4) rem = 4;                      \
            BITS &= (1u << rem) - 1u;                                          \
            if (BITS & 1u) C0 = __ldg(cols + (base));                          \
            if (BITS & 2u) C1 = __ldg(cols + (base) + 1);                      \
            if (BITS & 4u) C2 = __ldg(cols + (base) + 2);                      \
            if (BITS & 8u) C3 = __ldg(cols + (base) + 3);                      \
        }                                                                      \
    }

    unsigned bits = 0u;
    int c0 = 0, c1 = 0, c2 = 0, c3 = 0;
    LOAD_BATCH(beg, bits, c0, c1, c2, c3)

    for (int i = beg; i < end; i += 4) {
        unsigned nbits = 0u;
        int d0 = 0, d1 = 0, d2 = 0, d3 = 0;
        LOAD_BATCH(i + 4, nbits, d0, d1, d2, d3)

        #define ACC_ONE(c, K)                                                  \
        if (bits & (K)) {                                                      \
            uint4 q = __ldg(xh + (size_t)(c) * 8 + sub);                       \
            float2 f0 = __half22float2(*(const __half2*)&q.x);                 \
            float2 f1 = __half22float2(*(const __half2*)&q.y);                 \
            float2 f2 = __half22float2(*(const __half2*)&q.z);                 \
            float2 f3 = __half22float2(*(const __half2*)&q.w);                 \
            a0.x += f0.x; a0.y += f0.y;                                        \
            a1.x += f1.x; a1.y += f1.y;                                        \
            a2.x += f2.x; a2.y += f2.y;                                        \
            a3.x += f3.x; a3.y += f3.y;                                        \
        }
        ACC_ONE(c0, 1u)
        ACC_ONE(c1, 2u)
        ACC_ONE(c2, 4u)
        ACC_ONE(c3, 8u)
        #undef ACC_ONE

        bits = nbits;
        c0 = d0; c1 = d1; c2 = d2; c3 = d3;
    }
    #undef LOAD_BATCH

    const float s = 1.25f;   // 1/keep, exact
    float4 f0 = make_float4(s * a0.x, s * a0.y, s * a1.x, s * a1.y);
    float4 f1 = make_float4(s * a2.x, s * a2.y, s * a3.x, s * a3.y);
    *(float4*)(yf + (size_t)grp * NE + sub * 8)     = f0;
    *(float4*)(yf + (size_t)grp * NE + sub * 8 + 4) = f1;
}

// ---------------------------------------------------------------------------
// Launch
// ---------------------------------------------------------------------------
extern "C" void kernel_launch(void* const* d_in, const int* in_sizes, int n_in,
                              void* d_out, int out_size) {
    // Classify inputs by element count (robust to metadata ordering).
    const float* item_emb = nullptr;
    const void*  s_trip[3] = {nullptr, nullptr, nullptr};   // vals, rows, cols
    const void*  u_trip[3] = {nullptr, nullptr, nullptr};   // vals, rows, cols
    int si = 0, ui = 0;
    for (int k = 0; k < n_in; k++) {
        if (in_sizes[k] == NI * NE)      item_emb = (const float*)d_in[k];
        else if (in_sizes[k] == NNZ_S)   { if (si < 3) s_trip[si++] = d_in[k]; }
        else if (in_sizes[k] == NNZ_U)   { if (ui < 3) u_trip[ui++] = d_in[k]; }
    }
    const float* S_vals   = (const float*)s_trip[0];
    const int*   S_rows   = (const int*)  s_trip[1];
    const int*   S_cols   = (const int*)  s_trip[2];
    const int*   urm_rows = (const int*)  u_trip[1];
    const int*   urm_cols = (const int*)  u_trip[2];

    float* out_user = (float*)d_out;                       // [NU, NE]
    float* out_x    = (float*)d_out + (size_t)NU * NE;     // [NI, NE]

    // Resolve device-global scratch addresses (host side).
    uint4 *xh0, *xh1;
    unsigned *mask;
    int *s_rowptr, *u_rowptr;
    cudaGetSymbolAddress((void**)&xh0,      g_xh0);
    cudaGetSymbolAddress((void**)&xh1,      g_xh1);
    cudaGetSymbolAddress((void**)&mask,     g_mask);
    cudaGetSymbolAddress((void**)&s_rowptr, g_s_rowptr);
    cudaGetSymbolAddress((void**)&u_rowptr, g_u_rowptr);

    // Fused prologue: dropout mask + rowptrs + item_emb->half, one launch
    prologue_kernel<<<UVM_BLOCKS + RP_BLOCKS + CV_BLOCKS, BT>>>(
        mask, S_rows, urm_rows, s_rowptr, u_rowptr, item_emb, (__half2*)xh0);

    // 3-hop item-graph convolution (8-lane group per row: 32 rows / block)
    const int RPB = BT / 8;
    dim3 gridS((NI + RPB - 1) / RPB);
    spmm_h_kernel<true, false><<<gridS, BT>>>(
        s_rowptr, S_cols, S_vals, xh0, xh1, nullptr, NI);
    spmm_h_kernel<true, false><<<gridS, BT>>>(
        s_rowptr, S_cols, S_vals, xh1, xh0, nullptr, NI);
    spmm_h_kernel<true, true><<<gridS, BT>>>(
        s_rowptr, S_cols, S_vals, xh0, xh1, out_x, NI);

    // user_emb = (dropout(URM)) @ x — bitmask dropout, half gathers
    dim3 gridU((NU + RPB - 1) / RPB);
    spmm_u_kernel<<<gridU, BT>>>(u_rowptr, urm_cols, mask, xh1, out_user, NU);
}

// round 13
// speedup vs baseline: 1.0524x; 1.0524x over previous
#include <cuda_runtime.h>
#include <cuda_fp16.h>
#include <cstdint>

// Problem constants
#define NI      100000      // item count
#define NU      131072      // user count
#define NE      64          // embedding size
#define NNZ_S   1500000     // I * TOPK
#define NNZ_U   4194304     // user-item interactions (= 2^22)

#define BT 256

// Prologue region sizes (rowptr + convert only; mask gen lives in the hops)
#define RP_TOTAL    ((NI + 1) + (NU + 1))
#define RP_BLOCKS   ((RP_TOTAL + BT - 1) / BT)
#define CV_TOTAL    (NI * NE / 2)             // one half2 per thread
#define CV_BLOCKS   ((CV_TOTAL + BT - 1) / BT)

#define MASK_WORDS  (NNZ_U / 32)              // 131072 ballot words

// ---------------------------------------------------------------------------
// Static device scratch (allocation-free rule)
// x stored as half: one row = 64 halves = 8 uint4.
// ---------------------------------------------------------------------------
__device__ uint4    g_xh0[NI * NE / 8];       // 12.8 MB (half storage)
__device__ uint4    g_xh1[NI * NE / 8];       // 12.8 MB
__device__ unsigned g_mask[MASK_WORDS + 1];   // 512 KB keep-bits (+1 pad word)
__device__ int      g_s_rowptr[NI + 1];
__device__ int      g_u_rowptr[NU + 1];

// ---------------------------------------------------------------------------
// threefry2x32 (exact JAX implementation, key = (0, 42))
// ---------------------------------------------------------------------------
__device__ __forceinline__ uint32_t rotl32(uint32_t x, int d) {
    return (x << d) | (x >> (32 - d));
}

__device__ __forceinline__ void threefry2x32(uint32_t k0, uint32_t k1,
                                             uint32_t x0, uint32_t x1,
                                             uint32_t& o0, uint32_t& o1) {
    uint32_t ks2 = k0 ^ k1 ^ 0x1BD11BDAu;
    x0 += k0; x1 += k1;
    x0 += x1; x1 = rotl32(x1, 13); x1 ^= x0;
    x0 += x1; x1 = rotl32(x1, 15); x1 ^= x0;
    x0 += x1; x1 = rotl32(x1, 26); x1 ^= x0;
    x0 += x1; x1 = rotl32(x1,  6); x1 ^= x0;
    x0 += k1; x1 += ks2 + 1u;
    x0 += x1; x1 = rotl32(x1, 17); x1 ^= x0;
    x0 += x1; x1 = rotl32(x1, 29); x1 ^= x0;
    x0 += x1; x1 = rotl32(x1, 16); x1 ^= x0;
    x0 += x1; x1 = rotl32(x1, 24); x1 ^= x0;
    x0 += ks2; x1 += k0 + 2u;
    x0 += x1; x1 = rotl32(x1, 13); x1 ^= x0;
    x0 += x1; x1 = rotl32(x1, 15); x1 ^= x0;
    x0 += x1; x1 = rotl32(x1, 26); x1 ^= x0;
    x0 += x1; x1 = rotl32(x1,  6); x1 ^= x0;
    x0 += k0; x1 += k1 + 3u;
    x0 += x1; x1 = rotl32(x1, 17); x1 ^= x0;
    x0 += x1; x1 = rotl32(x1, 29); x1 ^= x0;
    x0 += x1; x1 = rotl32(x1, 16); x1 ^= x0;
    x0 += x1; x1 = rotl32(x1, 24); x1 ^= x0;
    x0 += k1; x1 += ks2 + 4u;
    x0 += x1; x1 = rotl32(x1, 13); x1 ^= x0;
    x0 += x1; x1 = rotl32(x1, 15); x1 ^= x0;
    x0 += x1; x1 = rotl32(x1, 26); x1 ^= x0;
    x0 += x1; x1 = rotl32(x1,  6); x1 ^= x0;
    x0 += ks2; x1 += k0 + 5u;
    o0 = x0; o1 = x1;
}

// Per-block mask slice: this block computes nwords ballot words starting at
// word0; warp w takes words w, w+8, ... Each lane evaluates one edge.
__device__ __forceinline__ void mask_block_work(unsigned* __restrict__ mask,
                                                int word0, int nwords, int tid) {
    int wi = tid >> 5, lane = tid & 31;
    for (int w = wi; w < nwords; w += BT / 32) {
        int word = word0 + w;
        int i = word * 32 + lane;
        uint32_t o0, o1;
        threefry2x32(0u, 42u, 0u, (uint32_t)i, o0, o1);
        uint32_t bits = o0 ^ o1;
        float u = __uint_as_float((bits >> 9) | 0x3F800000u) - 1.0f;
        unsigned bal = __ballot_sync(0xFFFFFFFFu, u < 0.8f);
        if (lane == 0) mask[word] = bal;
    }
}

// ---------------------------------------------------------------------------
// Prologue: CSR row-pointer build (S then URM) + item_emb fp32 -> half.
// ---------------------------------------------------------------------------
__global__ void prologue_kernel(unsigned* __restrict__ mask,
                                const int* __restrict__ s_rows,
                                const int* __restrict__ u_rows,
                                int* __restrict__ s_rowptr,
                                int* __restrict__ u_rowptr,
                                const float* __restrict__ item_emb,
                                __half2* __restrict__ xh) {
    int b = blockIdx.x;
    if (b < RP_BLOCKS) {
        int t = b * BT + (int)threadIdx.x;
        if (t == 0) mask[MASK_WORDS] = 0u;       // pad word (value unused)
        if (t <= NI) {
            int lo = 0, hi = NNZ_S;
            while (lo < hi) {
                int mid = (lo + hi) >> 1;
                if (s_rows[mid] < t) lo = mid + 1; else hi = mid;
            }
            s_rowptr[t] = lo;
        }
        int r = t - (NI + 1);
        if (r >= 0 && r <= NU) {
            int lo = 0, hi = NNZ_U;
            while (lo < hi) {
                int mid = (lo + hi) >> 1;
                if (u_rows[mid] < r) lo = mid + 1; else hi = mid;
            }
            u_rowptr[r] = lo;
        }
    } else {
        int t = (b - RP_BLOCKS) * BT + (int)threadIdx.x;
        if (t >= CV_TOTAL) return;
        float2 f = *(const float2*)(item_emb + (size_t)t * 2);
        xh[t] = __float22half2_rn(f);
    }
}

// ---------------------------------------------------------------------------
// 8-lane-group-per-row segmented SpMM on half x (VERBATIM R10 core) with
// software-pipelined cols/vals. Each block additionally computes a small
// slice of the dropout bitmask (ALU work filling idle issue slots of this
// latency-bound kernel; no extra blocks, so no tail wave).
// ---------------------------------------------------------------------------
template <bool WRITE_H, bool WRITE_F>
__global__ void __launch_bounds__(256) spmm_h_kernel(
                            const int*   __restrict__ rowptr,
                            const int*   __restrict__ cols,
                            const float* __restrict__ vals,
                            const uint4* __restrict__ xh,
                            uint4*       __restrict__ yh,
                            float*       __restrict__ yf,
                            int n_rows,
                            unsigned*    __restrict__ mask,
                            int mask_word_base, int mask_words) {
    // Mask slice first (pure ALU; overlaps other blocks' memory latency).
    if (mask_words > 0) {
        int per = (mask_words + (int)gridDim.x - 1) / (int)gridDim.x;
        int w0  = (int)blockIdx.x * per;
        int nw  = mask_words - w0; if (nw > per) nw = per;
        if (nw > 0) mask_block_work(mask, mask_word_base + w0, nw, (int)threadIdx.x);
    }

    int grp = (int)((blockIdx.x * blockDim.x + threadIdx.x) >> 3);  // row id
    int sub = threadIdx.x & 7;                                      // uint4 slot
    if (grp >= n_rows) return;

    int beg = rowptr[grp];
    int end = rowptr[grp + 1];

    float2 a0 = {0.f, 0.f}, a1 = {0.f, 0.f}, a2 = {0.f, 0.f}, a3 = {0.f, 0.f};

    // Preload first index batch
    int   c0 = 0, c1 = 0, c2 = 0, c3 = 0;
    float v0 = 0.f, v1 = 0.f, v2 = 0.f, v3 = 0.f;
    if (beg     < end) { c0 = __ldg(cols + beg);     v0 = __ldg(vals + beg);     }
    if (beg + 1 < end) { c1 = __ldg(cols + beg + 1); v1 = __ldg(vals + beg + 1); }
    if (beg + 2 < end) { c2 = __ldg(cols + beg + 2); v2 = __ldg(vals + beg + 2); }
    if (beg + 3 < end) { c3 = __ldg(cols + beg + 3); v3 = __ldg(vals + beg + 3); }

    for (int i = beg; i < end; i += 4) {
        // Prefetch next index batch (independent of current gathers)
        int n = i + 4;
        int   d0 = 0, d1 = 0, d2 = 0, d3 = 0;
        float w0 = 0.f, w1 = 0.f, w2 = 0.f, w3 = 0.f;
        if (n     < end) { d0 = __ldg(cols + n);     w0 = __ldg(vals + n);     }
        if (n + 1 < end) { d1 = __ldg(cols + n + 1); w1 = __ldg(vals + n + 1); }
        if (n + 2 < end) { d2 = __ldg(cols + n + 2); w2 = __ldg(vals + n + 2); }
        if (n + 3 < end) { d3 = __ldg(cols + n + 3); w3 = __ldg(vals + n + 3); }

        #define ACC_ONE(c, v)                                                  \
        {                                                                      \
            uint4 q = __ldg(xh + (size_t)(c) * 8 + sub);                       \
            float2 f0 = __half22float2(*(const __half2*)&q.x);                 \
            float2 f1 = __half22float2(*(const __half2*)&q.y);                 \
            float2 f2 = __half22float2(*(const __half2*)&q.z);                 \
            float2 f3 = __half22float2(*(const __half2*)&q.w);                 \
            a0.x = fmaf((v), f0.x, a0.x); a0.y = fmaf((v), f0.y, a0.y);        \
            a1.x = fmaf((v), f1.x, a1.x); a1.y = fmaf((v), f1.y, a1.y);        \
            a2.x = fmaf((v), f2.x, a2.x); a2.y = fmaf((v), f2.y, a2.y);        \
            a3.x = fmaf((v), f3.x, a3.x); a3.y = fmaf((v), f3.y, a3.y);        \
        }
        ACC_ONE(c0, v0)
        ACC_ONE(c1, v1)
        ACC_ONE(c2, v2)
        ACC_ONE(c3, v3)
        #undef ACC_ONE

        c0 = d0; c1 = d1; c2 = d2; c3 = d3;
        v0 = w0; v1 = w1; v2 = w2; v3 = w3;
    }

    if (WRITE_H) {
        __half2 h0 = __float22half2_rn(a0);
        __half2 h1 = __float22half2_rn(a1);
        __half2 h2 = __float22half2_rn(a2);
        __half2 h3 = __float22half2_rn(a3);
        uint4 q;
        q.x = *(const uint32_t*)&h0;
        q.y = *(const uint32_t*)&h1;
        q.z = *(const uint32_t*)&h2;
        q.w = *(const uint32_t*)&h3;
        yh[(size_t)grp * 8 + sub] = q;
    }
    if (WRITE_F) {
        float4 f0 = make_float4(a0.x, a0.y, a1.x, a1.y);
        float4 f1 = make_float4(a2.x, a2.y, a3.x, a3.y);
        *(float4*)(yf + (size_t)grp * NE + sub * 8)     = f0;
        *(float4*)(yf + (size_t)grp * NE + sub * 8 + 4) = f1;
    }
}

// ---------------------------------------------------------------------------
// U-spmm (VERBATIM R10): index-stream pipelining; dropout via bitmask with
// funnelshift. Kept edges accumulate unscaled; exact 1.25 scale at the end.
// ---------------------------------------------------------------------------
__global__ void __launch_bounds__(256) spmm_u_kernel(
                            const int*      __restrict__ rowptr,
                            const int*      __restrict__ cols,
                            const unsigned* __restrict__ mask,
                            const uint4*    __restrict__ xh,
                            float*          __restrict__ yf,
                            int n_rows) {
    int grp = (int)((blockIdx.x * blockDim.x + threadIdx.x) >> 3);  // row id
    int sub = threadIdx.x & 7;                                      // uint4 slot
    if (grp >= n_rows) return;

    int beg = rowptr[grp];
    int end = rowptr[grp + 1];

    float2 a0 = {0.f, 0.f}, a1 = {0.f, 0.f}, a2 = {0.f, 0.f}, a3 = {0.f, 0.f};

    #define LOAD_BATCH(base, BITS, C0, C1, C2, C3)                             \
    {                                                                          \
        if ((base) < end) {                                                    \
            unsigned w  = (unsigned)(base) >> 5;                               \
            unsigned sh = (unsigned)(base) & 31u;                              \
            unsigned m0 = __ldg(mask + w);                                     \
            unsigned m1 = __ldg(mask + w + 1);                                 \
            BITS = __funnelshift_r(m0, m1, sh);                                \
            int rem = end - (base); if (rem > 4) rem = 4;                      \
            BITS &= (1u << rem) - 1u;                                          \
            if (BITS & 1u) C0 = __ldg(cols + (base));                          \
            if (BITS & 2u) C1 = __ldg(cols + (base) + 1);                      \
            if (BITS & 4u) C2 = __ldg(cols + (base) + 2);                      \
            if (BITS & 8u) C3 = __ldg(cols + (base) + 3);                      \
        }                                                                      \
    }

    unsigned bits = 0u;
    int c0 = 0, c1 = 0, c2 = 0, c3 = 0;
    LOAD_BATCH(beg, bits, c0, c1, c2, c3)

    for (int i = beg; i < end; i += 4) {
        unsigned nbits = 0u;
        int d0 = 0, d1 = 0, d2 = 0, d3 = 0;
        LOAD_BATCH(i + 4, nbits, d0, d1, d2, d3)

        #define ACC_ONE(c, K)                                                  \
        if (bits & (K)) {                                                      \
            uint4 q = __ldg(xh + (size_t)(c) * 8 + sub);                       \
            float2 f0 = __half22float2(*(const __half2*)&q.x);                 \
            float2 f1 = __half22float2(*(const __half2*)&q.y);                 \
            float2 f2 = __half22float2(*(const __half2*)&q.z);                 \
            float2 f3 = __half22float2(*(const __half2*)&q.w);                 \
            a0.x += f0.x; a0.y += f0.y;                                        \
            a1.x += f1.x; a1.y += f1.y;                                        \
            a2.x += f2.x; a2.y += f2.y;                                        \
            a3.x += f3.x; a3.y += f3.y;                                        \
        }
        ACC_ONE(c0, 1u)
        ACC_ONE(c1, 2u)
        ACC_ONE(c2, 4u)
        ACC_ONE(c3, 8u)
        #undef ACC_ONE

        bits = nbits;
        c0 = d0; c1 = d1; c2 = d2; c3 = d3;
    }
    #undef LOAD_BATCH

    const float s = 1.25f;   // 1/keep, exact
    float4 f0 = make_float4(s * a0.x, s * a0.y, s * a1.x, s * a1.y);
    float4 f1 = make_float4(s * a2.x, s * a2.y, s * a3.x, s * a3.y);
    *(float4*)(yf + (size_t)grp * NE + sub * 8)     = f0;
    *(float4*)(yf + (size_t)grp * NE + sub * 8 + 4) = f1;
}

// ---------------------------------------------------------------------------
// Launch
// ---------------------------------------------------------------------------
extern "C" void kernel_launch(void* const* d_in, const int* in_sizes, int n_in,
                              void* d_out, int out_size) {
    // Classify inputs by element count (robust to metadata ordering).
    const float* item_emb = nullptr;
    const void*  s_trip[3] = {nullptr, nullptr, nullptr};   // vals, rows, cols
    const void*  u_trip[3] = {nullptr, nullptr, nullptr};   // vals, rows, cols
    int si = 0, ui = 0;
    for (int k = 0; k < n_in; k++) {
        if (in_sizes[k] == NI * NE)      item_emb = (const float*)d_in[k];
        else if (in_sizes[k] == NNZ_S)   { if (si < 3) s_trip[si++] = d_in[k]; }
        else if (in_sizes[k] == NNZ_U)   { if (ui < 3) u_trip[ui++] = d_in[k]; }
    }
    const float* S_vals   = (const float*)s_trip[0];
    const int*   S_rows   = (const int*)  s_trip[1];
    const int*   S_cols   = (const int*)  s_trip[2];
    const int*   urm_rows = (const int*)  u_trip[1];
    const int*   urm_cols = (const int*)  u_trip[2];

    float* out_user = (float*)d_out;                       // [NU, NE]
    float* out_x    = (float*)d_out + (size_t)NU * NE;     // [NI, NE]

    // Resolve device-global scratch addresses (host side).
    uint4 *xh0, *xh1;
    unsigned *mask;
    int *s_rowptr, *u_rowptr;
    cudaGetSymbolAddress((void**)&xh0,      g_xh0);
    cudaGetSymbolAddress((void**)&xh1,      g_xh1);
    cudaGetSymbolAddress((void**)&mask,     g_mask);
    cudaGetSymbolAddress((void**)&s_rowptr, g_s_rowptr);
    cudaGetSymbolAddress((void**)&u_rowptr, g_u_rowptr);

    // Prologue: rowptrs + item_emb->half (mask gen smeared across the hops)
    prologue_kernel<<<RP_BLOCKS + CV_BLOCKS, BT>>>(
        mask, S_rows, urm_rows, s_rowptr, u_rowptr, item_emb, (__half2*)xh0);

    // 3-hop item-graph convolution (8-lane group per row: 32 rows / block).
    // Each hop also generates a third of the dropout bitmask in-block.
    const int RPB = BT / 8;
    dim3 gridS((NI + RPB - 1) / RPB);
    const int MW1 = (MASK_WORDS + 2) / 3;                 // 43691
    const int MW2 = MW1;                                  // 43691
    const int MW3 = MASK_WORDS - MW1 - MW2;               // 43690

    spmm_h_kernel<true, false><<<gridS, BT>>>(
        s_rowptr, S_cols, S_vals, xh0, xh1, nullptr, NI, mask, 0, MW1);
    spmm_h_kernel<true, false><<<gridS, BT>>>(
        s_rowptr, S_cols, S_vals, xh1, xh0, nullptr, NI, mask, MW1, MW2);
    spmm_h_kernel<true, true><<<gridS, BT>>>(
        s_rowptr, S_cols, S_vals, xh0, xh1, out_x, NI, mask, MW1 + MW2, MW3);

    // user_emb = (dropout(URM)) @ x — bitmask dropout, half gathers
    dim3 gridU((NU + RPB - 1) / RPB);
    spmm_u_kernel<<<gridU, BT>>>(u_rowptr, urm_cols, mask, xh1, out_user, NU);
}